// round 2
// baseline (speedup 1.0000x reference)
#include <cuda_runtime.h>
#include <cuda_bf16.h>
#include <cstdint>

// ---------------------------------------------------------------------------
// Problem constants
// ---------------------------------------------------------------------------
#define MODEL_DIM 2048
#define N_HEADS   16
#define LATENT    512
#define DHR       64
#define DK        128   // MODEL_DIM / N_HEADS
#define BB        4
#define TT        2048
#define MROWS     (BB*TT)          // 8192
#define DQK       (DK + DHR)       // 192

// ---------------------------------------------------------------------------
// Scratch (static __device__ arrays -- no allocation allowed)
// ---------------------------------------------------------------------------
__device__ float g_down[(size_t)MROWS * 1024];          // [8192,1024]  (cKV | cq)
__device__ float g_vk  [(size_t)MROWS * 4096];          // [8192,4096]  (v|k per head)
__device__ float g_qc  [(size_t)MROWS * 2048];          // [8192,2048]
__device__ float g_qrp [(size_t)MROWS * 1024];          // [8192,1024]
__device__ float g_krp [(size_t)MROWS * 64];            // [8192,64]
__device__ float g_qf  [(size_t)BB*N_HEADS*TT*DQK];     // [b,h,t,192]
__device__ float g_kf  [(size_t)BB*N_HEADS*TT*DQK];     // [b,h,t,192]
__device__ float g_vf  [(size_t)BB*N_HEADS*TT*DK];      // [b,h,t,128]
__device__ float g_ao  [(size_t)MROWS * 2048];          // attention out, [row, h*128+d]

// ---------------------------------------------------------------------------
// Generic SGEMM + bias:  C[M,N] = A[M,K](lda) @ B[K,N] + bias[N]
// 128x128x8 tile, 256 threads, 8x8 micro-tile (interleaved columns).
// ---------------------------------------------------------------------------
#define GBM 128
#define GBN 128
#define GBK 8

__global__ __launch_bounds__(256)
void sgemm_bias_kernel(const float* __restrict__ A, int lda,
                       const float* __restrict__ Bw,
                       const float* __restrict__ bias,
                       float* __restrict__ C,
                       int M, int N, int K)
{
    __shared__ float As[GBK][GBM];
    __shared__ float Bs[GBK][GBN];

    const int tid = threadIdx.x;
    const int m0  = blockIdx.y * GBM;
    const int n0  = blockIdx.x * GBN;
    const int ty  = tid >> 4;            // 0..15
    const int tx  = tid & 15;            // 0..15

    const int aRow = tid >> 1;           // 0..127
    const int aCol = (tid & 1) * 4;      // 0 or 4
    const int bRow = tid >> 5;           // 0..7
    const int bCol = (tid & 31) * 4;     // 0..124

    float acc[8][8];
#pragma unroll
    for (int i = 0; i < 8; i++)
#pragma unroll
        for (int j = 0; j < 8; j++) acc[i][j] = 0.f;

    for (int k0 = 0; k0 < K; k0 += GBK) {
        // --- load A tile (M rows are always full multiples here) ---
        float4 a4 = *reinterpret_cast<const float4*>(
            &A[(size_t)(m0 + aRow) * lda + k0 + aCol]);
        As[aCol + 0][aRow] = a4.x;
        As[aCol + 1][aRow] = a4.y;
        As[aCol + 2][aRow] = a4.z;
        As[aCol + 3][aRow] = a4.w;

        // --- load B tile (guard N, e.g. N=64 for W_kr) ---
        const int ncol = n0 + bCol;
        float4 b4;
        if (ncol + 4 <= N) {
            b4 = *reinterpret_cast<const float4*>(
                &Bw[(size_t)(k0 + bRow) * N + ncol]);
        } else {
            const size_t base = (size_t)(k0 + bRow) * N;
            b4.x = (ncol + 0 < N) ? Bw[base + ncol + 0] : 0.f;
            b4.y = (ncol + 1 < N) ? Bw[base + ncol + 1] : 0.f;
            b4.z = (ncol + 2 < N) ? Bw[base + ncol + 2] : 0.f;
            b4.w = (ncol + 3 < N) ? Bw[base + ncol + 3] : 0.f;
        }
        *reinterpret_cast<float4*>(&Bs[bRow][bCol]) = b4;

        __syncthreads();

#pragma unroll
        for (int kk = 0; kk < GBK; ++kk) {
            float4 a0 = *reinterpret_cast<const float4*>(&As[kk][ty * 8]);
            float4 a1 = *reinterpret_cast<const float4*>(&As[kk][ty * 8 + 4]);
            float rm[8] = {a0.x, a0.y, a0.z, a0.w, a1.x, a1.y, a1.z, a1.w};
            float rn[8];
#pragma unroll
            for (int j = 0; j < 8; j++) rn[j] = Bs[kk][tx + 16 * j];
#pragma unroll
            for (int i = 0; i < 8; i++)
#pragma unroll
                for (int j = 0; j < 8; j++)
                    acc[i][j] = fmaf(rm[i], rn[j], acc[i][j]);
        }
        __syncthreads();
    }

    // --- epilogue: bias + store ---
#pragma unroll
    for (int j = 0; j < 8; j++) {
        const int col = n0 + tx + 16 * j;
        if (col < N) {
            const float bv = bias[col];
#pragma unroll
            for (int i = 0; i < 8; i++) {
                const size_t row = (size_t)(m0 + ty * 8 + i);
                C[row * (size_t)N + col] = acc[i][j] + bv;
            }
        }
    }
}

// ---------------------------------------------------------------------------
// Pack q/k into [b,h,t,192] with RoPE applied to the DHR tail.
// ---------------------------------------------------------------------------
__global__ void pack_qk_kernel(const float* __restrict__ qc,
                               const float* __restrict__ qrp,
                               const float* __restrict__ vk,
                               const float* __restrict__ krp,
                               float* __restrict__ qf,
                               float* __restrict__ kf)
{
    const size_t total = (size_t)BB * N_HEADS * TT * DQK;
    size_t idx = (size_t)blockIdx.x * blockDim.x + threadIdx.x;
    if (idx >= total) return;

    const int d  = (int)(idx % DQK);
    size_t r1    = idx / DQK;
    const int t  = (int)(r1 % TT);
    size_t r2    = r1 / TT;
    const int h  = (int)(r2 % N_HEADS);
    const int b  = (int)(r2 / N_HEADS);
    const size_t row = (size_t)b * TT + t;

    float qv, kv;
    if (d < DK) {
        qv = qc[row * 2048 + h * DK + d];
        kv = vk[row * 4096 + h * 256 + DK + d];
    } else {
        const int j  = d - DK;
        const int i2 = j >> 1;
        // theta = 10000^(-(j//2)/32)
        const float theta = expf(-(float)i2 * (9.210340371976184f / 32.0f));
        float sn, cs;
        sincosf((float)t * theta, &sn, &cs);
        const float xq = qrp[row * 1024 + h * DHR + j];
        const float xk = krp[row * 64 + j];
        if (j & 1) {  // odd: rot = +x[j-1]
            const float xq2 = qrp[row * 1024 + h * DHR + j - 1];
            const float xk2 = krp[row * 64 + j - 1];
            qv = xq * cs + xq2 * sn;
            kv = xk * cs + xk2 * sn;
        } else {      // even: rot = -x[j+1]
            const float xq2 = qrp[row * 1024 + h * DHR + j + 1];
            const float xk2 = krp[row * 64 + j + 1];
            qv = xq * cs - xq2 * sn;
            kv = xk * cs - xk2 * sn;
        }
    }
    qf[idx] = qv;
    kf[idx] = kv;
}

__global__ void pack_v_kernel(const float* __restrict__ vk,
                              float* __restrict__ vf)
{
    const size_t total = (size_t)BB * N_HEADS * TT * DK;
    size_t idx = (size_t)blockIdx.x * blockDim.x + threadIdx.x;
    if (idx >= total) return;
    const int d = (int)(idx % DK);
    size_t r1   = idx / DK;
    const int t = (int)(r1 % TT);
    size_t r2   = r1 / TT;
    const int h = (int)(r2 % N_HEADS);
    const int b = (int)(r2 / N_HEADS);
    const size_t row = (size_t)b * TT + t;
    vf[idx] = vk[row * 4096 + h * 256 + d];
}

// ---------------------------------------------------------------------------
// Flash attention (fp32, no mask).
// BM=64 q rows, BN=64 kv cols, d_qk=192, d_v=128, 128 threads.
// Thread (ty 0..7, tx 0..15): rows ty*8+i, interleaved cols tx+16*j.
// K tile padded to stride 193 so strided LDS are conflict-free.
// ---------------------------------------------------------------------------
#define FBM 64
#define FBN 64
#define FSMEM ((64*192 + 64*193 + 64*128 + 64*64) * 4)

__global__ __launch_bounds__(128)
void flash_kernel(const float* __restrict__ Q, const float* __restrict__ Kg,
                  const float* __restrict__ V, float* __restrict__ O)
{
    extern __shared__ float fsm[];
    float* Qs = fsm;                  // [64][192]
    float* Ks = Qs + 64 * 192;        // [64][193]
    float* Vs = Ks + 64 * 193;        // [64][128]
    float* Ps = Vs + 64 * 128;        // [64][64]

    const int tid = threadIdx.x;
    const int ty  = tid >> 4;         // 0..7
    const int tx  = tid & 15;         // 0..15
    const int h   = blockIdx.y;
    const int b   = blockIdx.z;
    const int q0  = blockIdx.x * FBM;
    const size_t bh = (size_t)b * N_HEADS + h;

    const float* Qb = Q  + bh * (size_t)TT * DQK + (size_t)q0 * DQK;
    const float* Kb = Kg + bh * (size_t)TT * DQK;
    const float* Vb = V  + bh * (size_t)TT * DK;

    // load Q tile once
    for (int i = tid; i < FBM * (DQK / 4); i += 128) {
        int r = i / 48, c = (i - r * 48) * 4;
        *reinterpret_cast<float4*>(&Qs[r * 192 + c]) =
            *reinterpret_cast<const float4*>(&Qb[(size_t)r * DQK + c]);
    }

    float m_i[8], l_i[8], o_acc[8][8];
#pragma unroll
    for (int i = 0; i < 8; i++) {
        m_i[i] = -1e30f;
        l_i[i] = 0.f;
#pragma unroll
        for (int j = 0; j < 8; j++) o_acc[i][j] = 0.f;
    }

    const float scale = 0.08838834764831845f;  // 1/sqrt(128)

    for (int s0 = 0; s0 < TT; s0 += FBN) {
        __syncthreads();
        // load K tile (scalar stores, stride 193)
        for (int i = tid; i < FBN * (DQK / 4); i += 128) {
            int r = i / 48, c = (i - r * 48) * 4;
            float4 v4 = *reinterpret_cast<const float4*>(
                &Kb[(size_t)(s0 + r) * DQK + c]);
            float* kp = &Ks[r * 193 + c];
            kp[0] = v4.x; kp[1] = v4.y; kp[2] = v4.z; kp[3] = v4.w;
        }
        // load V tile
        for (int i = tid; i < FBN * (DK / 4); i += 128) {
            int r = i / 32, c = (i - r * 32) * 4;
            *reinterpret_cast<float4*>(&Vs[r * 128 + c]) =
                *reinterpret_cast<const float4*>(&Vb[(size_t)(s0 + r) * DK + c]);
        }
        __syncthreads();

        // ---- S = Q K^T ----
        float s_acc[8][4];
#pragma unroll
        for (int i = 0; i < 8; i++)
#pragma unroll
            for (int j = 0; j < 4; j++) s_acc[i][j] = 0.f;

        for (int d = 0; d < DQK; d += 4) {
            float4 rq[8];
#pragma unroll
            for (int i = 0; i < 8; i++)
                rq[i] = *reinterpret_cast<const float4*>(&Qs[(ty * 8 + i) * 192 + d]);
#pragma unroll
            for (int j = 0; j < 4; j++) {
                const float* kp = &Ks[(tx + 16 * j) * 193 + d];
                const float k0 = kp[0], k1 = kp[1], k2 = kp[2], k3 = kp[3];
#pragma unroll
                for (int i = 0; i < 8; i++) {
                    s_acc[i][j] = fmaf(rq[i].x, k0, s_acc[i][j]);
                    s_acc[i][j] = fmaf(rq[i].y, k1, s_acc[i][j]);
                    s_acc[i][j] = fmaf(rq[i].z, k2, s_acc[i][j]);
                    s_acc[i][j] = fmaf(rq[i].w, k3, s_acc[i][j]);
                }
            }
        }

        // ---- online softmax ----
#pragma unroll
        for (int i = 0; i < 8; i++) {
#pragma unroll
            for (int j = 0; j < 4; j++) s_acc[i][j] *= scale;
            float mt = fmaxf(fmaxf(s_acc[i][0], s_acc[i][1]),
                             fmaxf(s_acc[i][2], s_acc[i][3]));
#pragma unroll
            for (int off = 8; off; off >>= 1)
                mt = fmaxf(mt, __shfl_xor_sync(0xffffffffu, mt, off));
            const float mnew = fmaxf(m_i[i], mt);
            const float corr = expf(m_i[i] - mnew);
            float rs = 0.f;
#pragma unroll
            for (int j = 0; j < 4; j++) {
                const float p = expf(s_acc[i][j] - mnew);
                rs += p;
                Ps[(ty * 8 + i) * 64 + tx + 16 * j] = p;
            }
#pragma unroll
            for (int off = 8; off; off >>= 1)
                rs += __shfl_xor_sync(0xffffffffu, rs, off);
            l_i[i] = l_i[i] * corr + rs;
            m_i[i] = mnew;
#pragma unroll
            for (int jj = 0; jj < 8; jj++) o_acc[i][jj] *= corr;
        }
        // Ps rows are written and read by lanes of the same warp but different
        // lane IDs; shfl is not a memory fence — __syncwarp() provides the
        // shared-memory ordering guarantee.
        __syncwarp();

        // ---- O += P @ V ----
        for (int s = 0; s < FBN; s++) {
            float vv[8];
#pragma unroll
            for (int j = 0; j < 8; j++) vv[j] = Vs[s * 128 + tx + 16 * j];
#pragma unroll
            for (int i = 0; i < 8; i++) {
                const float pv = Ps[(ty * 8 + i) * 64 + s];
#pragma unroll
                for (int j = 0; j < 8; j++)
                    o_acc[i][j] = fmaf(pv, vv[j], o_acc[i][j]);
            }
        }
    }

    // ---- epilogue: normalize + write [row, h*128+col] ----
#pragma unroll
    for (int i = 0; i < 8; i++) {
        const float inv = 1.f / l_i[i];
        const size_t row = (size_t)b * TT + q0 + ty * 8 + i;
#pragma unroll
        for (int j = 0; j < 8; j++)
            O[row * 2048 + h * DK + tx + 16 * j] = o_acc[i][j] * inv;
    }
}

// ---------------------------------------------------------------------------
// Host launcher
// ---------------------------------------------------------------------------
static void launch_gemm(const float* A, int lda, const float* Bw,
                        const float* bias, float* C, int M, int N, int K)
{
    dim3 grid((N + GBN - 1) / GBN, M / GBM);
    sgemm_bias_kernel<<<grid, 256>>>(A, lda, Bw, bias, C, M, N, K);
}

extern "C" void kernel_launch(void* const* d_in, const int* in_sizes, int n_in,
                              void* d_out, int out_size)
{
    const float* x      = (const float*)d_in[0];
    const float* W_down = (const float*)d_in[1];
    const float* b_down = (const float*)d_in[2];
    const float* W_uKV  = (const float*)d_in[3];
    const float* b_uKV  = (const float*)d_in[4];
    const float* W_uQ   = (const float*)d_in[5];
    const float* b_uQ   = (const float*)d_in[6];
    const float* W_kr   = (const float*)d_in[7];
    const float* b_kr   = (const float*)d_in[8];
    const float* W_qr   = (const float*)d_in[9];
    const float* b_qr   = (const float*)d_in[10];
    const float* W_out  = (const float*)d_in[11];
    const float* b_out  = (const float*)d_in[12];
    float* out = (float*)d_out;

    float *down, *vk, *qc, *qrp, *krp, *qf, *kf, *vf, *ao;
    cudaGetSymbolAddress((void**)&down, g_down);
    cudaGetSymbolAddress((void**)&vk,   g_vk);
    cudaGetSymbolAddress((void**)&qc,   g_qc);
    cudaGetSymbolAddress((void**)&qrp,  g_qrp);
    cudaGetSymbolAddress((void**)&krp,  g_krp);
    cudaGetSymbolAddress((void**)&qf,   g_qf);
    cudaGetSymbolAddress((void**)&kf,   g_kf);
    cudaGetSymbolAddress((void**)&vf,   g_vf);
    cudaGetSymbolAddress((void**)&ao,   g_ao);

    cudaFuncSetAttribute(flash_kernel,
                         cudaFuncAttributeMaxDynamicSharedMemorySize, FSMEM);

    // 1) down = x @ W_down + b_down            [8192,1024]
    launch_gemm(x, MODEL_DIM, W_down, b_down, down, MROWS, 1024, MODEL_DIM);
    // 2) v_k = cKV @ W_uKV + b_uKV             [8192,4096]
    launch_gemm(down, 1024, W_uKV, b_uKV, vk, MROWS, 4096, LATENT);
    // 3) q = cq @ W_uQ + b_uQ                  [8192,2048]
    launch_gemm(down + LATENT, 1024, W_uQ, b_uQ, qc, MROWS, 2048, LATENT);
    // 4) qR = x @ W_qr + b_qr                  [8192,1024]
    launch_gemm(x, MODEL_DIM, W_qr, b_qr, qrp, MROWS, 1024, MODEL_DIM);
    // 5) kR = x @ W_kr + b_kr                  [8192,64]
    launch_gemm(x, MODEL_DIM, W_kr, b_kr, krp, MROWS, 64, MODEL_DIM);

    // 6) pack + RoPE
    {
        const size_t nqk = (size_t)BB * N_HEADS * TT * DQK;
        pack_qk_kernel<<<(unsigned)((nqk + 255) / 256), 256>>>(qc, qrp, vk, krp, qf, kf);
        const size_t nv = (size_t)BB * N_HEADS * TT * DK;
        pack_v_kernel<<<(unsigned)((nv + 255) / 256), 256>>>(vk, vf);
    }

    // 7) attention
    {
        dim3 fgrid(TT / FBM, N_HEADS, BB);
        flash_kernel<<<fgrid, 128, FSMEM>>>(qf, kf, vf, ao);
    }

    // 8) out = attn @ W_out + b_out  -> d_out  [8192,2048]
    launch_gemm(ao, 2048, W_out, b_out, out, MROWS, 2048, MODEL_DIM);
}

// round 17
// speedup vs baseline: 2.4679x; 2.4679x over previous
#include <cuda_runtime.h>
#include <cuda_bf16.h>
#include <cstdint>

// ---------------------------------------------------------------------------
// Problem constants
// ---------------------------------------------------------------------------
#define MODEL_DIM 2048
#define N_HEADS   16
#define LATENT    512
#define DHR       64
#define DK        128
#define BB        4
#define TT        2048
#define MROWS     (BB*TT)          // 8192
#define DQK       (DK + DHR)       // 192

typedef __nv_bfloat16  bf16;
typedef __nv_bfloat162 bf162;

// ---------------------------------------------------------------------------
// Scratch (static __device__ arrays -- no allocation allowed)
// ---------------------------------------------------------------------------
__device__ float g_vk [(size_t)MROWS * 4096];   // v|k per head (fp32)
__device__ float g_qc [(size_t)MROWS * 2048];
__device__ float g_qrp[(size_t)MROWS * 1024];
__device__ float g_krp[(size_t)MROWS * 64];

// flash inputs, bf16 hi/lo  [b,h,t,d]
__device__ bf16 g_qfh[(size_t)BB*N_HEADS*TT*DQK], g_qfl[(size_t)BB*N_HEADS*TT*DQK];
__device__ bf16 g_kfh[(size_t)BB*N_HEADS*TT*DQK], g_kfl[(size_t)BB*N_HEADS*TT*DQK];
__device__ bf16 g_vfh[(size_t)BB*N_HEADS*TT*DK],  g_vfl[(size_t)BB*N_HEADS*TT*DK];

// bf16 hi/lo splits for GEMMs
__device__ bf16 g_xh [(size_t)MROWS*2048],  g_xl [(size_t)MROWS*2048];
__device__ bf16 g_dnh[(size_t)MROWS*1024],  g_dnl[(size_t)MROWS*1024];
__device__ bf16 g_aoh[(size_t)MROWS*2048],  g_aol[(size_t)MROWS*2048];
__device__ bf16 g_wdh[2048*1024],  g_wdl[2048*1024];
__device__ bf16 g_wkvh[512*4096],  g_wkvl[512*4096];
__device__ bf16 g_wqh [512*2048],  g_wql [512*2048];
__device__ bf16 g_wqrh[2048*1024], g_wqrl[2048*1024];
__device__ bf16 g_woh [2048*2048], g_wol [2048*2048];

// ---------------------------------------------------------------------------
// helpers
// ---------------------------------------------------------------------------
__device__ __forceinline__ uint32_t pack_bf162(float a, float b)
{
    bf162 v = __float22bfloat162_rn(make_float2(a, b));
    return *reinterpret_cast<uint32_t*>(&v);
}
__device__ __forceinline__ float bf16_residual(float v)
{
    return v - __bfloat162float(__float2bfloat16(v));
}

// fp32 -> (hi, lo) bf16 split
__global__ void split_kernel(const float2* __restrict__ src,
                             bf162* __restrict__ h, bf162* __restrict__ l,
                             size_t n2)
{
    size_t i = (size_t)blockIdx.x * blockDim.x + threadIdx.x;
    if (i >= n2) return;
    float2 v = src[i];
    bf16 h0 = __float2bfloat16(v.x);
    bf16 h1 = __float2bfloat16(v.y);
    bf162 hv; hv.x = h0; hv.y = h1;
    bf162 lv;
    lv.x = __float2bfloat16(v.x - __bfloat162float(h0));
    lv.y = __float2bfloat16(v.y - __bfloat162float(h1));
    h[i] = hv;
    l[i] = lv;
}

// ---------------------------------------------------------------------------
// mma.sync helpers
// ---------------------------------------------------------------------------
__device__ __forceinline__ void ldm_x4(uint32_t r[4], uint32_t addr)
{
    asm volatile("ldmatrix.sync.aligned.m8n8.x4.shared.b16 {%0,%1,%2,%3}, [%4];"
                 : "=r"(r[0]), "=r"(r[1]), "=r"(r[2]), "=r"(r[3]) : "r"(addr));
}
__device__ __forceinline__ void ldm_x4t(uint32_t r[4], uint32_t addr)
{
    asm volatile("ldmatrix.sync.aligned.m8n8.x4.trans.shared.b16 {%0,%1,%2,%3}, [%4];"
                 : "=r"(r[0]), "=r"(r[1]), "=r"(r[2]), "=r"(r[3]) : "r"(addr));
}
__device__ __forceinline__ void mma16816(float d[4], const uint32_t a[4],
                                         uint32_t b0, uint32_t b1)
{
    asm volatile(
        "mma.sync.aligned.m16n8k16.row.col.f32.bf16.bf16.f32 "
        "{%0,%1,%2,%3}, {%4,%5,%6,%7}, {%8,%9}, {%0,%1,%2,%3};"
        : "+f"(d[0]), "+f"(d[1]), "+f"(d[2]), "+f"(d[3])
        : "r"(a[0]), "r"(a[1]), "r"(a[2]), "r"(a[3]), "r"(b0), "r"(b1));
}

// ---------------------------------------------------------------------------
// Split-bf16 tensor-core GEMM (3 passes hh, hl, lh)
// ---------------------------------------------------------------------------
#define TBM 128
#define TBN 128
#define TBK 64

__global__ __launch_bounds__(256)
void mma_gemm_kernel(const bf16* __restrict__ Ah, const bf16* __restrict__ Al,
                     int lda,
                     const bf16* __restrict__ Bh, const bf16* __restrict__ Bl,
                     const float* __restrict__ bias,
                     float* __restrict__ Cf,
                     bf16* __restrict__ Ch, bf16* __restrict__ Cl,
                     int ldc, int M, int N, int K)
{
    __shared__ __align__(16) bf16 As[TBM * TBK];
    __shared__ __align__(16) bf16 Bs[TBK * TBN];

    const int tid  = threadIdx.x;
    const int lane = tid & 31;
    const int warp = tid >> 5;
    const int warpM = warp >> 2;
    const int warpN = warp & 3;
    const int m0 = blockIdx.y * TBM;
    const int n0 = blockIdx.x * TBN;

    const int nIterK    = K / TBK;
    const int totalIter = 3 * nIterK;

    float acc[4][4][4];
#pragma unroll
    for (int a = 0; a < 4; a++)
#pragma unroll
        for (int b = 0; b < 4; b++)
#pragma unroll
            for (int c = 0; c < 4; c++) acc[a][b][c] = 0.f;

    uint4 ra[4], rb[4];
    int aRow[4], aChk[4], bRow[4], bChk[4];
#pragma unroll
    for (int r = 0; r < 4; r++) {
        int ia = tid + 256 * r;
        aRow[r] = ia >> 3;  aChk[r] = ia & 7;
        bRow[r] = ia >> 4;  bChk[r] = ia & 15;
    }

    const uint32_t AsB = (uint32_t)__cvta_generic_to_shared(As);
    const uint32_t BsB = (uint32_t)__cvta_generic_to_shared(Bs);

    auto loadTile = [&](int it) {
        const int pass = it / nIterK;
        const int kk   = (it - pass * nIterK) * TBK;
        const bf16* Ap = (pass < 2) ? Ah : Al;
        const bf16* Bp = (pass == 1) ? Bl : Bh;
#pragma unroll
        for (int r = 0; r < 4; r++) {
            ra[r] = *reinterpret_cast<const uint4*>(
                Ap + (size_t)(m0 + aRow[r]) * lda + kk + aChk[r] * 8);
            rb[r] = *reinterpret_cast<const uint4*>(
                Bp + (size_t)(kk + bRow[r]) * N + n0 + bChk[r] * 8);
        }
    };
    auto storeTile = [&]() {
#pragma unroll
        for (int r = 0; r < 4; r++) {
            reinterpret_cast<uint4*>(As)[aRow[r] * 8 + (aChk[r] ^ (aRow[r] & 7))] = ra[r];
            reinterpret_cast<uint4*>(Bs)[bRow[r] * 16 + (bChk[r] ^ (bRow[r] & 7))] = rb[r];
        }
    };
    const int lr = lane & 7;
    const int lh = (lane >> 3) & 1;
    const int lc = lane >> 4;
    auto compute = [&]() {
#pragma unroll
        for (int ks = 0; ks < 4; ks++) {
            uint32_t afr[4][4];
#pragma unroll
            for (int mt = 0; mt < 4; mt++) {
                const int mrow = warpM * 64 + mt * 16 + lr + lh * 8;
                const int cc   = ks * 2 + lc;
                ldm_x4(afr[mt], AsB + ((mrow * 8 + (cc ^ (mrow & 7))) << 4));
            }
            uint32_t bfr[2][4];
#pragma unroll
            for (int np = 0; np < 2; np++) {
                const int krow = ks * 16 + lr + lh * 8;
                const int cc   = ((warpN * 32 + np * 16) >> 3) + lc;
                ldm_x4t(bfr[np], BsB + ((krow * 16 + (cc ^ (krow & 7))) << 4));
            }
#pragma unroll
            for (int mt = 0; mt < 4; mt++)
#pragma unroll
                for (int nt = 0; nt < 4; nt++)
                    mma16816(acc[mt][nt], afr[mt],
                             bfr[nt >> 1][(nt & 1) * 2],
                             bfr[nt >> 1][(nt & 1) * 2 + 1]);
        }
    };

    loadTile(0);
    storeTile();
    __syncthreads();
    for (int it = 0; it < totalIter; ++it) {
        if (it + 1 < totalIter) loadTile(it + 1);
        compute();
        __syncthreads();
        if (it + 1 < totalIter) {
            storeTile();
            __syncthreads();
        }
    }

    const int g  = lane >> 2;
    const int cp = (lane & 3) * 2;
#pragma unroll
    for (int mt = 0; mt < 4; mt++) {
#pragma unroll
        for (int nt = 0; nt < 4; nt++) {
            const int col  = n0 + warpN * 32 + nt * 8 + cp;
            const int row0 = m0 + warpM * 64 + mt * 16 + g;
            const float b0 = bias[col], b1 = bias[col + 1];
            const float v00 = acc[mt][nt][0] + b0;
            const float v01 = acc[mt][nt][1] + b1;
            const float v10 = acc[mt][nt][2] + b0;
            const float v11 = acc[mt][nt][3] + b1;
            if (Cf) {
                *reinterpret_cast<float2*>(&Cf[(size_t)row0 * ldc + col]) =
                    make_float2(v00, v01);
                *reinterpret_cast<float2*>(&Cf[(size_t)(row0 + 8) * ldc + col]) =
                    make_float2(v10, v11);
            } else {
                bf16 h00 = __float2bfloat16(v00), h01 = __float2bfloat16(v01);
                bf16 h10 = __float2bfloat16(v10), h11 = __float2bfloat16(v11);
                bf162 hv0; hv0.x = h00; hv0.y = h01;
                bf162 hv1; hv1.x = h10; hv1.y = h11;
                bf162 lv0, lv1;
                lv0.x = __float2bfloat16(v00 - __bfloat162float(h00));
                lv0.y = __float2bfloat16(v01 - __bfloat162float(h01));
                lv1.x = __float2bfloat16(v10 - __bfloat162float(h10));
                lv1.y = __float2bfloat16(v11 - __bfloat162float(h11));
                *reinterpret_cast<bf162*>(&Ch[(size_t)row0 * ldc + col])       = hv0;
                *reinterpret_cast<bf162*>(&Ch[(size_t)(row0 + 8) * ldc + col]) = hv1;
                *reinterpret_cast<bf162*>(&Cl[(size_t)row0 * ldc + col])       = lv0;
                *reinterpret_cast<bf162*>(&Cl[(size_t)(row0 + 8) * ldc + col]) = lv1;
            }
        }
    }
}

// ---------------------------------------------------------------------------
// fp32 SIMT SGEMM (only for the small N=64 kR projection)
// ---------------------------------------------------------------------------
#define GBM 128
#define GBN 128
#define GBK 8

__global__ __launch_bounds__(256)
void sgemm_bias_kernel(const float* __restrict__ A, int lda,
                       const float* __restrict__ Bw,
                       const float* __restrict__ bias,
                       float* __restrict__ C,
                       int M, int N, int K)
{
    __shared__ float As[GBK][GBM];
    __shared__ float Bs[GBK][GBN];

    const int tid = threadIdx.x;
    const int m0  = blockIdx.y * GBM;
    const int n0  = blockIdx.x * GBN;
    const int ty  = tid >> 4;
    const int tx  = tid & 15;
    const int aRow = tid >> 1;
    const int aCol = (tid & 1) * 4;
    const int bRow = tid >> 5;
    const int bCol = (tid & 31) * 4;

    float acc[8][8];
#pragma unroll
    for (int i = 0; i < 8; i++)
#pragma unroll
        for (int j = 0; j < 8; j++) acc[i][j] = 0.f;

    for (int k0 = 0; k0 < K; k0 += GBK) {
        float4 a4 = *reinterpret_cast<const float4*>(
            &A[(size_t)(m0 + aRow) * lda + k0 + aCol]);
        As[aCol + 0][aRow] = a4.x;
        As[aCol + 1][aRow] = a4.y;
        As[aCol + 2][aRow] = a4.z;
        As[aCol + 3][aRow] = a4.w;

        const int ncol = n0 + bCol;
        float4 b4;
        if (ncol + 4 <= N) {
            b4 = *reinterpret_cast<const float4*>(&Bw[(size_t)(k0 + bRow) * N + ncol]);
        } else {
            const size_t base = (size_t)(k0 + bRow) * N;
            b4.x = (ncol + 0 < N) ? Bw[base + ncol + 0] : 0.f;
            b4.y = (ncol + 1 < N) ? Bw[base + ncol + 1] : 0.f;
            b4.z = (ncol + 2 < N) ? Bw[base + ncol + 2] : 0.f;
            b4.w = (ncol + 3 < N) ? Bw[base + ncol + 3] : 0.f;
        }
        *reinterpret_cast<float4*>(&Bs[bRow][bCol]) = b4;
        __syncthreads();

#pragma unroll
        for (int kk = 0; kk < GBK; ++kk) {
            float4 a0 = *reinterpret_cast<const float4*>(&As[kk][ty * 8]);
            float4 a1 = *reinterpret_cast<const float4*>(&As[kk][ty * 8 + 4]);
            float rm[8] = {a0.x, a0.y, a0.z, a0.w, a1.x, a1.y, a1.z, a1.w};
            float rn[8];
#pragma unroll
            for (int j = 0; j < 8; j++) rn[j] = Bs[kk][tx + 16 * j];
#pragma unroll
            for (int i = 0; i < 8; i++)
#pragma unroll
                for (int j = 0; j < 8; j++)
                    acc[i][j] = fmaf(rm[i], rn[j], acc[i][j]);
        }
        __syncthreads();
    }

#pragma unroll
    for (int j = 0; j < 8; j++) {
        const int col = n0 + tx + 16 * j;
        if (col < N) {
            const float bv = bias[col];
#pragma unroll
            for (int i = 0; i < 8; i++) {
                const size_t row = (size_t)(m0 + ty * 8 + i);
                C[row * (size_t)N + col] = acc[i][j] + bv;
            }
        }
    }
}

// ---------------------------------------------------------------------------
// Pack q/k into [b,h,t,192] bf16 hi/lo with RoPE on the DHR tail.
// ---------------------------------------------------------------------------
__global__ void pack_qk_kernel(const float* __restrict__ qc,
                               const float* __restrict__ qrp,
                               const float* __restrict__ vk,
                               const float* __restrict__ krp,
                               bf16* __restrict__ qh, bf16* __restrict__ ql,
                               bf16* __restrict__ kh, bf16* __restrict__ kl)
{
    const size_t total = (size_t)BB * N_HEADS * TT * DQK;
    size_t idx = (size_t)blockIdx.x * blockDim.x + threadIdx.x;
    if (idx >= total) return;

    const int d  = (int)(idx % DQK);
    size_t r1    = idx / DQK;
    const int t  = (int)(r1 % TT);
    size_t r2    = r1 / TT;
    const int h  = (int)(r2 % N_HEADS);
    const int b  = (int)(r2 / N_HEADS);
    const size_t row = (size_t)b * TT + t;

    float qv, kv;
    if (d < DK) {
        qv = qc[row * 2048 + h * DK + d];
        kv = vk[row * 4096 + h * 256 + DK + d];
    } else {
        const int j  = d - DK;
        const int i2 = j >> 1;
        const float theta = expf(-(float)i2 * (9.210340371976184f / 32.0f));
        float sn, cs;
        sincosf((float)t * theta, &sn, &cs);
        const float xq = qrp[row * 1024 + h * DHR + j];
        const float xk = krp[row * 64 + j];
        if (j & 1) {
            const float xq2 = qrp[row * 1024 + h * DHR + j - 1];
            const float xk2 = krp[row * 64 + j - 1];
            qv = xq * cs + xq2 * sn;
            kv = xk * cs + xk2 * sn;
        } else {
            const float xq2 = qrp[row * 1024 + h * DHR + j + 1];
            const float xk2 = krp[row * 64 + j + 1];
            qv = xq * cs - xq2 * sn;
            kv = xk * cs - xk2 * sn;
        }
    }
    bf16 qhv = __float2bfloat16(qv);
    bf16 khv = __float2bfloat16(kv);
    qh[idx] = qhv; ql[idx] = __float2bfloat16(qv - __bfloat162float(qhv));
    kh[idx] = khv; kl[idx] = __float2bfloat16(kv - __bfloat162float(khv));
}

__global__ void pack_v_kernel(const float* __restrict__ vk,
                              bf16* __restrict__ vh, bf16* __restrict__ vl)
{
    const size_t total = (size_t)BB * N_HEADS * TT * DK;
    size_t idx = (size_t)blockIdx.x * blockDim.x + threadIdx.x;
    if (idx >= total) return;
    const int d = (int)(idx % DK);
    size_t r1   = idx / DK;
    const int t = (int)(r1 % TT);
    size_t r2   = r1 / TT;
    const int h = (int)(r2 % N_HEADS);
    const int b = (int)(r2 / N_HEADS);
    const size_t row = (size_t)b * TT + t;
    const float v = vk[row * 4096 + h * 256 + d];
    bf16 hv = __float2bfloat16(v);
    vh[idx] = hv;
    vl[idx] = __float2bfloat16(v - __bfloat162float(hv));
}

// ---------------------------------------------------------------------------
// Tensor-core flash attention, split-bf16 (3 passes each for QK^T and PV).
// BM=64, BN=64, 4 warps (one per 16 q rows). smem 128KB.
// ---------------------------------------------------------------------------
#define FLASH_SMEM ((64*DQK*4 + 64*DK*2) * 2)   // bytes = 131072

__global__ __launch_bounds__(128)
void flash_mma_kernel(const bf16* __restrict__ Qh, const bf16* __restrict__ Ql,
                      const bf16* __restrict__ Kh, const bf16* __restrict__ Kl,
                      const bf16* __restrict__ Vh, const bf16* __restrict__ Vl,
                      bf16* __restrict__ Oh, bf16* __restrict__ Ol)
{
    extern __shared__ __align__(16) bf16 fsm[];
    bf16* Qhs = fsm;                   // [64][192] swizzled
    bf16* Qls = Qhs + 64 * DQK;
    bf16* Khs = Qls + 64 * DQK;
    bf16* Kls = Khs + 64 * DQK;
    bf16* Vhs = Kls + 64 * DQK;        // [64][128] swizzled
    bf16* Vls = Vhs + 64 * DK;

    const int tid  = threadIdx.x;
    const int lane = tid & 31;
    const int warp = tid >> 5;
    const int h  = blockIdx.y;
    const int b  = blockIdx.z;
    const int q0 = blockIdx.x * 64;
    const size_t bh = (size_t)b * N_HEADS + h;

    const bf16* QhB = Qh + bh * (size_t)TT * DQK + (size_t)q0 * DQK;
    const bf16* QlB = Ql + bh * (size_t)TT * DQK + (size_t)q0 * DQK;
    const bf16* KhB = Kh + bh * (size_t)TT * DQK;
    const bf16* KlB = Kl + bh * (size_t)TT * DQK;
    const bf16* VhB = Vh + bh * (size_t)TT * DK;
    const bf16* VlB = Vl + bh * (size_t)TT * DK;

    const uint32_t QhsB = (uint32_t)__cvta_generic_to_shared(Qhs);
    const uint32_t QlsB = (uint32_t)__cvta_generic_to_shared(Qls);
    const uint32_t KhsB = (uint32_t)__cvta_generic_to_shared(Khs);
    const uint32_t KlsB = (uint32_t)__cvta_generic_to_shared(Kls);
    const uint32_t VhsB = (uint32_t)__cvta_generic_to_shared(Vhs);
    const uint32_t VlsB = (uint32_t)__cvta_generic_to_shared(Vls);

    // ---- load Q tiles (once), swizzled: chunk ^= row&7 ----
    for (int i = tid; i < 64 * 24; i += 128) {
        int r = i / 24, c = i % 24;
        int dst = r * 24 + (c ^ (r & 7));
        reinterpret_cast<uint4*>(Qhs)[dst] =
            *reinterpret_cast<const uint4*>(QhB + (size_t)r * DQK + c * 8);
        reinterpret_cast<uint4*>(Qls)[dst] =
            *reinterpret_cast<const uint4*>(QlB + (size_t)r * DQK + c * 8);
    }

    float m0v = -1e30f, m1v = -1e30f, l0v = 0.f, l1v = 0.f;
    float o_acc[16][4];
#pragma unroll
    for (int t = 0; t < 16; t++)
#pragma unroll
        for (int c = 0; c < 4; c++) o_acc[t][c] = 0.f;

    const float scale = 0.08838834764831845f;  // 1/sqrt(128)
    const int lrow = lane & 15;                // ldmatrix row within 16
    const int lcc  = lane >> 4;                // ldmatrix chunk select

    for (int s0 = 0; s0 < TT; s0 += 64) {
        __syncthreads();
        // ---- load K (hi/lo) and V (hi/lo) tiles ----
        for (int i = tid; i < 64 * 24; i += 128) {
            int r = i / 24, c = i % 24;
            int dst = r * 24 + (c ^ (r & 7));
            reinterpret_cast<uint4*>(Khs)[dst] =
                *reinterpret_cast<const uint4*>(KhB + (size_t)(s0 + r) * DQK + c * 8);
            reinterpret_cast<uint4*>(Kls)[dst] =
                *reinterpret_cast<const uint4*>(KlB + (size_t)(s0 + r) * DQK + c * 8);
        }
        for (int i = tid; i < 64 * 16; i += 128) {
            int r = i / 16, c = i % 16;
            int dst = r * 16 + (c ^ (r & 7));
            reinterpret_cast<uint4*>(Vhs)[dst] =
                *reinterpret_cast<const uint4*>(VhB + (size_t)(s0 + r) * DK + c * 8);
            reinterpret_cast<uint4*>(Vls)[dst] =
                *reinterpret_cast<const uint4*>(VlB + (size_t)(s0 + r) * DK + c * 8);
        }
        __syncthreads();

        // ---- S = Q K^T  (3-pass split) ----
        float sa[8][4];
#pragma unroll
        for (int j = 0; j < 8; j++)
#pragma unroll
            for (int c = 0; c < 4; c++) sa[j][c] = 0.f;

#pragma unroll
        for (int ks = 0; ks < 12; ks++) {
            const int mrow = warp * 16 + lrow;
            const int cc   = ks * 2 + lcc;
            uint32_t qh4[4], ql4[4];
            ldm_x4(qh4, QhsB + ((mrow * 24 + (cc ^ (mrow & 7))) << 4));
            ldm_x4(ql4, QlsB + ((mrow * 24 + (cc ^ (mrow & 7))) << 4));
#pragma unroll
            for (int sp = 0; sp < 4; sp++) {
                const int srow = sp * 16 + lrow;
                const int scc  = ks * 2 + lcc;
                uint32_t kh4[4], kl4[4];
                ldm_x4(kh4, KhsB + ((srow * 24 + (scc ^ (srow & 7))) << 4));
                ldm_x4(kl4, KlsB + ((srow * 24 + (scc ^ (srow & 7))) << 4));
                // non-trans K: n-tile even -> regs {0,2}, odd -> {1,3}
                mma16816(sa[2 * sp],     qh4, kh4[0], kh4[2]);
                mma16816(sa[2 * sp + 1], qh4, kh4[1], kh4[3]);
                mma16816(sa[2 * sp],     ql4, kh4[0], kh4[2]);
                mma16816(sa[2 * sp + 1], ql4, kh4[1], kh4[3]);
                mma16816(sa[2 * sp],     qh4, kl4[0], kl4[2]);
                mma16816(sa[2 * sp + 1], qh4, kl4[1], kl4[3]);
            }
        }

        // ---- online softmax (rows r0 = lane/4, r1 = r0+8 within warp tile) ----
        float mx0 = -1e30f, mx1 = -1e30f;
#pragma unroll
        for (int j = 0; j < 8; j++) {
#pragma unroll
            for (int c = 0; c < 4; c++) sa[j][c] *= scale;
            mx0 = fmaxf(mx0, fmaxf(sa[j][0], sa[j][1]));
            mx1 = fmaxf(mx1, fmaxf(sa[j][2], sa[j][3]));
        }
        mx0 = fmaxf(mx0, __shfl_xor_sync(0xffffffffu, mx0, 1));
        mx0 = fmaxf(mx0, __shfl_xor_sync(0xffffffffu, mx0, 2));
        mx1 = fmaxf(mx1, __shfl_xor_sync(0xffffffffu, mx1, 1));
        mx1 = fmaxf(mx1, __shfl_xor_sync(0xffffffffu, mx1, 2));
        const float mn0 = fmaxf(m0v, mx0);
        const float mn1 = fmaxf(m1v, mx1);
        const float cr0 = __expf(m0v - mn0);
        const float cr1 = __expf(m1v - mn1);
        float rs0 = 0.f, rs1 = 0.f;
#pragma unroll
        for (int j = 0; j < 8; j++) {
            sa[j][0] = __expf(sa[j][0] - mn0);
            sa[j][1] = __expf(sa[j][1] - mn0);
            sa[j][2] = __expf(sa[j][2] - mn1);
            sa[j][3] = __expf(sa[j][3] - mn1);
            rs0 += sa[j][0] + sa[j][1];
            rs1 += sa[j][2] + sa[j][3];
        }
        rs0 += __shfl_xor_sync(0xffffffffu, rs0, 1);
        rs0 += __shfl_xor_sync(0xffffffffu, rs0, 2);
        rs1 += __shfl_xor_sync(0xffffffffu, rs1, 1);
        rs1 += __shfl_xor_sync(0xffffffffu, rs1, 2);
        l0v = l0v * cr0 + rs0;
        l1v = l1v * cr1 + rs1;
        m0v = mn0; m1v = mn1;
#pragma unroll
        for (int t = 0; t < 16; t++) {
            o_acc[t][0] *= cr0; o_acc[t][1] *= cr0;
            o_acc[t][2] *= cr1; o_acc[t][3] *= cr1;
        }

        // ---- O += P V  (3-pass split; P repacked from C-layout to A-layout) ----
#pragma unroll
        for (int k = 0; k < 4; k++) {
            const int j0 = 2 * k, j1 = 2 * k + 1;
            uint32_t ah[4], al[4];
            ah[0] = pack_bf162(sa[j0][0], sa[j0][1]);
            ah[1] = pack_bf162(sa[j0][2], sa[j0][3]);
            ah[2] = pack_bf162(sa[j1][0], sa[j1][1]);
            ah[3] = pack_bf162(sa[j1][2], sa[j1][3]);
            al[0] = pack_bf162(bf16_residual(sa[j0][0]), bf16_residual(sa[j0][1]));
            al[1] = pack_bf162(bf16_residual(sa[j0][2]), bf16_residual(sa[j0][3]));
            al[2] = pack_bf162(bf16_residual(sa[j1][0]), bf16_residual(sa[j1][1]));
            al[3] = pack_bf162(bf16_residual(sa[j1][2]), bf16_residual(sa[j1][3]));
#pragma unroll
            for (int dp = 0; dp < 8; dp++) {
                const int krow = k * 16 + lrow;
                const int cc   = dp * 2 + lcc;
                uint32_t vh4[4], vl4[4];
                ldm_x4t(vh4, VhsB + ((krow * 16 + (cc ^ (krow & 7))) << 4));
                ldm_x4t(vl4, VlsB + ((krow * 16 + (cc ^ (krow & 7))) << 4));
                // trans V: n-tile even -> {0,1}, odd -> {2,3}
                mma16816(o_acc[2 * dp],     ah, vh4[0], vh4[1]);
                mma16816(o_acc[2 * dp + 1], ah, vh4[2], vh4[3]);
                mma16816(o_acc[2 * dp],     al, vh4[0], vh4[1]);
                mma16816(o_acc[2 * dp + 1], al, vh4[2], vh4[3]);
                mma16816(o_acc[2 * dp],     ah, vl4[0], vl4[1]);
                mma16816(o_acc[2 * dp + 1], ah, vl4[2], vl4[3]);
            }
        }
    }

    // ---- epilogue: normalize + hi/lo bf16 at [row, h*128+col] ----
    const float inv0 = 1.f / l0v;
    const float inv1 = 1.f / l1v;
    const size_t row0 = (size_t)b * TT + q0 + warp * 16 + (lane >> 2);
#pragma unroll
    for (int t = 0; t < 16; t++) {
        const int col = h * DK + t * 8 + 2 * (lane & 3);
        const float v0 = o_acc[t][0] * inv0;
        const float v1 = o_acc[t][1] * inv0;
        const float v2 = o_acc[t][2] * inv1;
        const float v3 = o_acc[t][3] * inv1;
        bf16 h0 = __float2bfloat16(v0), h1 = __float2bfloat16(v1);
        bf16 h2 = __float2bfloat16(v2), h3 = __float2bfloat16(v3);
        bf162 hv0; hv0.x = h0; hv0.y = h1;
        bf162 hv1; hv1.x = h2; hv1.y = h3;
        bf162 lv0, lv1;
        lv0.x = __float2bfloat16(v0 - __bfloat162float(h0));
        lv0.y = __float2bfloat16(v1 - __bfloat162float(h1));
        lv1.x = __float2bfloat16(v2 - __bfloat162float(h2));
        lv1.y = __float2bfloat16(v3 - __bfloat162float(h3));
        *reinterpret_cast<bf162*>(&Oh[row0 * 2048 + col])       = hv0;
        *reinterpret_cast<bf162*>(&Oh[(row0 + 8) * 2048 + col]) = hv1;
        *reinterpret_cast<bf162*>(&Ol[row0 * 2048 + col])       = lv0;
        *reinterpret_cast<bf162*>(&Ol[(row0 + 8) * 2048 + col]) = lv1;
    }
}

// ---------------------------------------------------------------------------
// Host launcher
// ---------------------------------------------------------------------------
static void launch_split(const float* src, bf16* h, bf16* l, size_t n)
{
    const size_t n2 = n / 2;
    split_kernel<<<(unsigned)((n2 + 255) / 256), 256>>>(
        (const float2*)src, (bf162*)h, (bf162*)l, n2);
}

static void launch_mma(const bf16* Ah, const bf16* Al, int lda,
                       const bf16* Bh, const bf16* Bl, const float* bias,
                       float* Cf, bf16* Ch, bf16* Cl, int ldc,
                       int M, int N, int K)
{
    dim3 grid(N / TBN, M / TBM);
    mma_gemm_kernel<<<grid, 256>>>(Ah, Al, lda, Bh, Bl, bias,
                                   Cf, Ch, Cl, ldc, M, N, K);
}

extern "C" void kernel_launch(void* const* d_in, const int* in_sizes, int n_in,
                              void* d_out, int out_size)
{
    const float* x      = (const float*)d_in[0];
    const float* W_down = (const float*)d_in[1];
    const float* b_down = (const float*)d_in[2];
    const float* W_uKV  = (const float*)d_in[3];
    const float* b_uKV  = (const float*)d_in[4];
    const float* W_uQ   = (const float*)d_in[5];
    const float* b_uQ   = (const float*)d_in[6];
    const float* W_kr   = (const float*)d_in[7];
    const float* b_kr   = (const float*)d_in[8];
    const float* W_qr   = (const float*)d_in[9];
    const float* b_qr   = (const float*)d_in[10];
    const float* W_out  = (const float*)d_in[11];
    const float* b_out  = (const float*)d_in[12];
    float* out = (float*)d_out;

    float *vk, *qc, *qrp, *krp;
    bf16 *qfh, *qfl, *kfh, *kfl, *vfh, *vfl;
    bf16 *xh, *xl, *dnh, *dnl, *aoh, *aol;
    bf16 *wdh, *wdl, *wkvh, *wkvl, *wqh, *wql, *wqrh, *wqrl, *woh, *wol;
    cudaGetSymbolAddress((void**)&vk,   g_vk);
    cudaGetSymbolAddress((void**)&qc,   g_qc);
    cudaGetSymbolAddress((void**)&qrp,  g_qrp);
    cudaGetSymbolAddress((void**)&krp,  g_krp);
    cudaGetSymbolAddress((void**)&qfh,  g_qfh);
    cudaGetSymbolAddress((void**)&qfl,  g_qfl);
    cudaGetSymbolAddress((void**)&kfh,  g_kfh);
    cudaGetSymbolAddress((void**)&kfl,  g_kfl);
    cudaGetSymbolAddress((void**)&vfh,  g_vfh);
    cudaGetSymbolAddress((void**)&vfl,  g_vfl);
    cudaGetSymbolAddress((void**)&xh,   g_xh);
    cudaGetSymbolAddress((void**)&xl,   g_xl);
    cudaGetSymbolAddress((void**)&dnh,  g_dnh);
    cudaGetSymbolAddress((void**)&dnl,  g_dnl);
    cudaGetSymbolAddress((void**)&aoh,  g_aoh);
    cudaGetSymbolAddress((void**)&aol,  g_aol);
    cudaGetSymbolAddress((void**)&wdh,  g_wdh);
    cudaGetSymbolAddress((void**)&wdl,  g_wdl);
    cudaGetSymbolAddress((void**)&wkvh, g_wkvh);
    cudaGetSymbolAddress((void**)&wkvl, g_wkvl);
    cudaGetSymbolAddress((void**)&wqh,  g_wqh);
    cudaGetSymbolAddress((void**)&wql,  g_wql);
    cudaGetSymbolAddress((void**)&wqrh, g_wqrh);
    cudaGetSymbolAddress((void**)&wqrl, g_wqrl);
    cudaGetSymbolAddress((void**)&woh,  g_woh);
    cudaGetSymbolAddress((void**)&wol,  g_wol);

    cudaFuncSetAttribute(flash_mma_kernel,
                         cudaFuncAttributeMaxDynamicSharedMemorySize, FLASH_SMEM);

    // 0) hi/lo splits of x and big weights
    launch_split(x,      xh,   xl,   (size_t)MROWS * 2048);
    launch_split(W_down, wdh,  wdl,  (size_t)2048 * 1024);
    launch_split(W_uKV,  wkvh, wkvl, (size_t)512 * 4096);
    launch_split(W_uQ,   wqh,  wql,  (size_t)512 * 2048);
    launch_split(W_qr,   wqrh, wqrl, (size_t)2048 * 1024);
    launch_split(W_out,  woh,  wol,  (size_t)2048 * 2048);

    // 1) down = x @ W_down + b_down  -> hi/lo bf16 [8192,1024]
    launch_mma(xh, xl, 2048, wdh, wdl, b_down,
               nullptr, dnh, dnl, 1024, MROWS, 1024, 2048);
    // 2) v_k = cKV @ W_uKV + b_uKV   -> fp32 [8192,4096]
    launch_mma(dnh, dnl, 1024, wkvh, wkvl, b_uKV,
               vk, nullptr, nullptr, 4096, MROWS, 4096, 512);
    // 3) q = cq @ W_uQ + b_uQ        -> fp32 [8192,2048]
    launch_mma(dnh + 512, dnl + 512, 1024, wqh, wql, b_uQ,
               qc, nullptr, nullptr, 2048, MROWS, 2048, 512);
    // 4) qR = x @ W_qr + b_qr        -> fp32 [8192,1024]
    launch_mma(xh, xl, 2048, wqrh, wqrl, b_qr,
               qrp, nullptr, nullptr, 1024, MROWS, 1024, 2048);
    // 5) kR = x @ W_kr + b_kr        -> fp32 [8192,64]  (small, SIMT)
    {
        dim3 grid(1, MROWS / GBM);
        sgemm_bias_kernel<<<grid, 256>>>(x, MODEL_DIM, W_kr, b_kr, krp,
                                         MROWS, 64, MODEL_DIM);
    }

    // 6) pack + RoPE -> bf16 hi/lo q,k,v
    {
        const size_t nqk = (size_t)BB * N_HEADS * TT * DQK;
        pack_qk_kernel<<<(unsigned)((nqk + 255) / 256), 256>>>(
            qc, qrp, vk, krp, qfh, qfl, kfh, kfl);
        const size_t nv = (size_t)BB * N_HEADS * TT * DK;
        pack_v_kernel<<<(unsigned)((nv + 255) / 256), 256>>>(vk, vfh, vfl);
    }

    // 7) tensor-core flash attention -> hi/lo bf16
    {
        dim3 fgrid(TT / 64, N_HEADS, BB);
        flash_mma_kernel<<<fgrid, 128, FLASH_SMEM>>>(
            qfh, qfl, kfh, kfl, vfh, vfl, aoh, aol);
    }

    // 8) out = attn @ W_out + b_out -> d_out fp32
    launch_mma(aoh, aol, 2048, woh, wol, b_out,
               out, nullptr, nullptr, 2048, MROWS, 2048, 2048);
}